// round 16
// baseline (speedup 1.0000x reference)
#include <cuda_runtime.h>
#include <cuda_bf16.h>
#include <cuda_fp16.h>
#include <cstdint>

#define RR   3
#define NN   50000
#define EE   200000
#define RN   (RR*NN)
#define RE   (RR*EE)
#define DIN  128
#define DHID 128
#define DOUT 64
#define NB   ((RN + 1023) / 1024)   // 147 scan blocks

// ---------------- scratch (device globals; no allocation allowed) ----------
__device__ int   g_deg_out[RN];
__device__ int   g_deg_in [RN];
__device__ float g_onorm  [RN];
__device__ float g_inorm  [RN];
__device__ int   g_rowptr [RN + 1];
__device__ int   g_pos    [RN];
__device__ int   g_colsrc [RE];
__device__ int   g_blocksum[NB];
__device__ int   g_blockoff[NB + 1];
__device__ __half g_Y1h[(size_t)RN * DHID];  // onorm-scaled transformed feats (fp16)
__device__ __half g_Hh [(size_t)NN * DHID];  // hidden after relu (fp16)
__device__ __half g_Y2h[(size_t)RN * DOUT];
__device__ __half g_W1T[RR * DHID * DIN];    // W1^T [r][n][k], fp16
__device__ __half g_W2T[RR * DOUT * DHID];   // W2^T [r][n][k], fp16

// ---------------- ptx helpers ------------------------------------------------
__device__ __forceinline__ uint32_t smem_u32(const void* p) {
    uint32_t a;
    asm("{ .reg .u64 t; cvta.to.shared.u64 t, %1; cvt.u32.u64 %0, t; }"
        : "=r"(a) : "l"(p));
    return a;
}
__device__ __forceinline__ void ldsm_x4(uint32_t& r0, uint32_t& r1,
                                        uint32_t& r2, uint32_t& r3, uint32_t a) {
    asm volatile("ldmatrix.sync.aligned.m8n8.x4.shared.b16 {%0,%1,%2,%3}, [%4];"
                 : "=r"(r0), "=r"(r1), "=r"(r2), "=r"(r3) : "r"(a));
}
__device__ __forceinline__ void ldsm_x2(uint32_t& r0, uint32_t& r1, uint32_t a) {
    asm volatile("ldmatrix.sync.aligned.m8n8.x2.shared.b16 {%0,%1}, [%2];"
                 : "=r"(r0), "=r"(r1) : "r"(a));
}
__device__ __forceinline__ void mma_f16(float* d, const uint32_t* a,
                                        const uint32_t* b) {
    asm volatile(
        "mma.sync.aligned.m16n8k16.row.col.f32.f16.f16.f32 "
        "{%0,%1,%2,%3}, {%4,%5,%6,%7}, {%8,%9}, {%0,%1,%2,%3};"
        : "+f"(d[0]), "+f"(d[1]), "+f"(d[2]), "+f"(d[3])
        : "r"(a[0]), "r"(a[1]), "r"(a[2]), "r"(a[3]), "r"(b[0]), "r"(b[1]));
}
__device__ __forceinline__ uint32_t h2u(__half2 v) {
    return *reinterpret_cast<uint32_t*>(&v);
}
__device__ __forceinline__ void cp_async16(uint32_t daddr, const void* src) {
    asm volatile("cp.async.cg.shared.global [%0], [%1], 16;"
                 :: "r"(daddr), "l"(src) : "memory");
}
__device__ __forceinline__ void cp_commit() {
    asm volatile("cp.async.commit_group;" ::: "memory");
}
__device__ __forceinline__ void cp_wait0() {
    asm volatile("cp.async.wait_group 0;" ::: "memory");
}

// ---------------- graph preprocessing ---------------------------------------
__global__ void zero_deg_kernel() {
    int i = blockIdx.x * blockDim.x + threadIdx.x;
    if (i < RN) { g_deg_out[i] = 0; g_deg_in[i] = 0; }
}

__global__ void count_deg_kernel(const int* __restrict__ src,
                                 const int* __restrict__ dst) {
    int e = blockIdx.x * blockDim.x + threadIdx.x;
    if (e >= EE) return;
    int r = blockIdx.y;
    int i = r * EE + e;
    atomicAdd(&g_deg_out[r * NN + src[i]], 1);
    atomicAdd(&g_deg_in [r * NN + dst[i]], 1);
}

__global__ void onorm_kernel() {
    int i = blockIdx.x * blockDim.x + threadIdx.x;
    if (i >= RN) return;
    int od = g_deg_out[i]; if (od < 1) od = 1;
    g_onorm[i] = rsqrtf((float)od);
}

__global__ void scan1_kernel() {
    __shared__ int sm[1024];
    const int t = threadIdx.x;
    const int i = blockIdx.x * 1024 + t;
    int v = (i < RN) ? g_deg_in[i] : 0;
    sm[t] = v;
    __syncthreads();
    #pragma unroll
    for (int off = 1; off < 1024; off <<= 1) {
        int u = (t >= off) ? sm[t - off] : 0;
        __syncthreads();
        sm[t] += u;
        __syncthreads();
    }
    if (i < RN) g_rowptr[i] = sm[t];
    if (t == 1023) g_blocksum[blockIdx.x] = sm[1023];
}

__global__ void scan2_kernel() {
    __shared__ int sm[256];
    const int t = threadIdx.x;
    int v = (t < NB) ? g_blocksum[t] : 0;
    sm[t] = v;
    __syncthreads();
    #pragma unroll
    for (int off = 1; off < 256; off <<= 1) {
        int u = (t >= off) ? sm[t - off] : 0;
        __syncthreads();
        sm[t] += u;
        __syncthreads();
    }
    if (t < NB) g_blockoff[t] = sm[t] - v;
    if (t == NB - 1) g_blockoff[NB] = sm[t];
}

// scan fixup + inorm (deg_in already in hand)
__global__ void scan3_kernel() {
    int i = blockIdx.x * blockDim.x + threadIdx.x;
    if (i == 0) g_rowptr[RN] = g_blockoff[NB];
    if (i >= RN) return;
    int d = g_deg_in[i];
    int excl = g_rowptr[i] - d + g_blockoff[i >> 10];
    g_rowptr[i] = excl;
    g_pos[i]    = excl;
    g_inorm[i]  = rsqrtf((float)(d < 1 ? 1 : d));
}

__global__ void fill_csr_kernel(const int* __restrict__ src,
                                const int* __restrict__ dst) {
    int e = blockIdx.x * blockDim.x + threadIdx.x;
    if (e >= EE) return;
    int r = blockIdx.y;
    int i = r * EE + e;
    int p = atomicAdd(&g_pos[r * NN + dst[i]], 1);
    g_colsrc[p] = src[i];
}

// transpose W to fp16: [r][K=128][Ndim] fp32 -> [r][Ndim][128] fp16
template <int Ndim>
__global__ void wtrans_kernel(const float* __restrict__ W,
                              __half* __restrict__ T) {
    int r = blockIdx.y;
    int i = blockIdx.x * 256 + threadIdx.x;
    if (i >= 128 * Ndim) return;
    int k = i / Ndim, n = i % Ndim;
    T[((size_t)r * Ndim + n) * 128 + k] =
        __float2half_rn(W[((size_t)r * 128 + k) * Ndim + n]);
}

// ---------------- fused HMMA fp16 GEMM: Y[r] = onorm_r ⊙ (A @ W[r]), r=0..2 -
// One CTA loads/converts its A tile ONCE, then loops relations with W_r
// double-buffered via cp.async (prefetch overlaps mma). 2 CTAs/SM.
template <int N, int LAYER>
__global__ void __launch_bounds__(256, 2)
mma_gemm_fused(const float* __restrict__ xin) {
    extern __shared__ char smem[];
    const __half* WT = (LAYER == 0) ? g_W1T : g_W2T;
    __half* Y = (LAYER == 0) ? g_Y1h : g_Y2h;

    constexpr int OFF_A   = 0;            // 128 rows x 256B = 32KB
    constexpr int OFF_B   = 128 * 256;    // two buffers of N*256B
    constexpr int B_BYTES = N * 256;

    const int t = threadIdx.x;
    const int row0 = blockIdx.x * 128;
    const uint32_t sbase = smem_u32(smem);

    // ---- prefetch B_0 via cp.async ----
    {
        const __half* Wr = WT;            // r = 0
        #pragma unroll
        for (int i = t; i < N * 16; i += 256) {
            int n = i >> 4, g = i & 15;
            uint32_t daddr = sbase + OFF_B + n * 256 + ((g ^ (n & 7)) << 4);
            cp_async16(daddr, Wr + (size_t)n * 128 + g * 8);
        }
        cp_commit();
    }
    // ---- A: layer0 = fp32->fp16 convert; layer1 = raw fp16 copy (once) ----
    #pragma unroll
    for (int i = t; i < 128 * 16; i += 256) {
        int m = i >> 4, g = i & 15;
        int grow = row0 + m;
        uint4 packed = make_uint4(0u, 0u, 0u, 0u);
        if (grow < NN) {
            if (LAYER == 0) {
                const float4* ap = (const float4*)(xin + (size_t)grow * 128 + g * 8);
                float4 v0 = ap[0], v1 = ap[1];
                packed = make_uint4(h2u(__floats2half2_rn(v0.x, v0.y)),
                                    h2u(__floats2half2_rn(v0.z, v0.w)),
                                    h2u(__floats2half2_rn(v1.x, v1.y)),
                                    h2u(__floats2half2_rn(v1.z, v1.w)));
            } else {
                packed = *(const uint4*)(g_Hh + (size_t)grow * 128 + g * 8);
            }
        }
        uint32_t off = m * 256 + ((g ^ (m & 7)) << 4);
        *(uint4*)(smem + OFF_A + off) = packed;
    }

    // ---- warp tiling ----
    constexpr int WM = (N == 128) ? 64 : 32;
    constexpr int WN = 32;
    constexpr int WX = N / WN;
    constexpr int MI = WM / 16, NI = WN / 8;
    const int wid = t >> 5, lane = t & 31;
    const int wm0 = (wid / WX) * WM;
    const int wn0 = (wid % WX) * WN;
    const int a_row = (lane & 15);
    const int a_kg  = (lane >> 4);
    const int b_n   = (lane & 7);
    const int b_kg  = ((lane >> 3) & 1);

    #pragma unroll
    for (int r = 0; r < RR; r++) {
        cp_wait0();           // B_r arrived
        __syncthreads();      // + A stores visible (r==0) / buffer reuse safe

        // prefetch B_{r+1} into the other buffer (overlaps mma below)
        if (r + 1 < RR) {
            const __half* Wr = WT + (size_t)(r + 1) * N * 128;
            uint32_t bufoff = OFF_B + ((r + 1) & 1) * B_BYTES;
            #pragma unroll
            for (int i = t; i < N * 16; i += 256) {
                int n = i >> 4, g = i & 15;
                uint32_t daddr = sbase + bufoff + n * 256 + ((g ^ (n & 7)) << 4);
                cp_async16(daddr, Wr + (size_t)n * 128 + g * 8);
            }
            cp_commit();
        }

        float acc[MI][NI][4];
        #pragma unroll
        for (int mi = 0; mi < MI; mi++)
            #pragma unroll
            for (int ni = 0; ni < NI; ni++)
                #pragma unroll
                for (int q = 0; q < 4; q++) acc[mi][ni][q] = 0.f;

        const uint32_t boff = OFF_B + (r & 1) * B_BYTES;
        #pragma unroll
        for (int ks = 0; ks < 8; ks++) {
            uint32_t ah[MI][4];
            #pragma unroll
            for (int mi = 0; mi < MI; mi++) {
                int row = wm0 + mi * 16 + a_row;
                int kg  = ks * 2 + a_kg;
                uint32_t off = row * 256 + ((kg ^ (row & 7)) << 4);
                ldsm_x4(ah[mi][0], ah[mi][1], ah[mi][2], ah[mi][3],
                        sbase + OFF_A + off);
            }
            uint32_t bh[NI][2];
            #pragma unroll
            for (int ni = 0; ni < NI; ni++) {
                int n  = wn0 + ni * 8 + b_n;
                int kg = ks * 2 + b_kg;
                uint32_t off = n * 256 + ((kg ^ (n & 7)) << 4);
                ldsm_x2(bh[ni][0], bh[ni][1], sbase + boff + off);
            }
            #pragma unroll
            for (int mi = 0; mi < MI; mi++)
                #pragma unroll
                for (int ni = 0; ni < NI; ni++)
                    mma_f16(acc[mi][ni], ah[mi], bh[ni]);
        }

        // ---- epilogue: scale rows by onorm, write fp16 Y[r] ----
        #pragma unroll
        for (int mi = 0; mi < MI; mi++) {
            int m0 = row0 + wm0 + mi * 16 + (lane >> 2);
            float on0 = (m0 < NN)     ? g_onorm[r * NN + m0]     : 0.f;
            float on1 = (m0 + 8 < NN) ? g_onorm[r * NN + m0 + 8] : 0.f;
            #pragma unroll
            for (int ni = 0; ni < NI; ni++) {
                int n = wn0 + ni * 8 + 2 * (lane & 3);
                if (m0 < NN)
                    *(__half2*)&Y[((size_t)r * NN + m0) * N + n] =
                        __floats2half2_rn(acc[mi][ni][0] * on0, acc[mi][ni][1] * on0);
                if (m0 + 8 < NN)
                    *(__half2*)&Y[((size_t)r * NN + m0 + 8) * N + n] =
                        __floats2half2_rn(acc[mi][ni][2] * on1, acc[mi][ni][3] * on1);
            }
        }
    }
}

// ---------------- aggregation: half-warp per 256B row, 2x unroll ------------
__global__ void agg1_kernel(const float* __restrict__ b1) {
    int gt   = blockIdx.x * blockDim.x + threadIdx.x;
    int n    = gt >> 5;
    int lane = gt & 31;
    if (n >= NN) return;
    const int hw = lane >> 4;      // half-warp id 0/1
    const int li = lane & 15;      // 16 lanes x 16B = 256B row

    float acc[8];
    #pragma unroll
    for (int i = 0; i < 8; i++) acc[i] = 0.f;

    #pragma unroll
    for (int r = 0; r < RR; r++) {
        int key = r * NN + n;
        int beg = g_rowptr[key];
        int end = g_rowptr[key + 1];
        const __half* Yr = g_Y1h + (size_t)r * NN * DHID;
        float s[8];
        #pragma unroll
        for (int i = 0; i < 8; i++) s[i] = 0.f;

        int j = beg + hw;
        for (; j + 2 < end; j += 4) {           // 2 rows per half-warp in flight
            int sn0 = g_colsrc[j];
            int sn1 = g_colsrc[j + 2];
            uint4 u0 = *(const uint4*)&Yr[(size_t)sn0 * DHID + li * 8];
            uint4 u1 = *(const uint4*)&Yr[(size_t)sn1 * DHID + li * 8];
            float2 a0 = __half22float2(*(const __half2*)&u0.x);
            float2 a1 = __half22float2(*(const __half2*)&u0.y);
            float2 a2 = __half22float2(*(const __half2*)&u0.z);
            float2 a3 = __half22float2(*(const __half2*)&u0.w);
            float2 c0 = __half22float2(*(const __half2*)&u1.x);
            float2 c1 = __half22float2(*(const __half2*)&u1.y);
            float2 c2 = __half22float2(*(const __half2*)&u1.z);
            float2 c3 = __half22float2(*(const __half2*)&u1.w);
            s[0] += a0.x + c0.x; s[1] += a0.y + c0.y;
            s[2] += a1.x + c1.x; s[3] += a1.y + c1.y;
            s[4] += a2.x + c2.x; s[5] += a2.y + c2.y;
            s[6] += a3.x + c3.x; s[7] += a3.y + c3.y;
        }
        if (j < end) {
            int sn = g_colsrc[j];
            uint4 u = *(const uint4*)&Yr[(size_t)sn * DHID + li * 8];
            float2 a0 = __half22float2(*(const __half2*)&u.x);
            float2 a1 = __half22float2(*(const __half2*)&u.y);
            float2 a2 = __half22float2(*(const __half2*)&u.z);
            float2 a3 = __half22float2(*(const __half2*)&u.w);
            s[0] += a0.x; s[1] += a0.y; s[2] += a1.x; s[3] += a1.y;
            s[4] += a2.x; s[5] += a2.y; s[6] += a3.x; s[7] += a3.y;
        }
        float inn = g_inorm[key];
        #pragma unroll
        for (int i = 0; i < 8; i++) acc[i] += inn * s[i];
    }
    // cross half-warp reduction
    #pragma unroll
    for (int i = 0; i < 8; i++)
        acc[i] += __shfl_xor_sync(0xffffffffu, acc[i], 16);

    int col = li * 8;
    #pragma unroll
    for (int i = 0; i < 8; i++) {
        acc[i] += b1[col + i] + b1[DHID + col + i] + b1[2 * DHID + col + i];
        acc[i] = fmaxf(acc[i], 0.f);
    }
    if (hw == 0) {
        __half2 p0 = __floats2half2_rn(acc[0], acc[1]);
        __half2 p1 = __floats2half2_rn(acc[2], acc[3]);
        __half2 p2 = __floats2half2_rn(acc[4], acc[5]);
        __half2 p3 = __floats2half2_rn(acc[6], acc[7]);
        *(uint4*)&g_Hh[(size_t)n * DHID + col] =
            make_uint4(h2u(p0), h2u(p1), h2u(p2), h2u(p3));
    }
}

// ---------------- aggregation 2: quarter-warp per 128B row ------------------
__global__ void agg2_kernel(const float* __restrict__ b2,
                            float* __restrict__ out) {
    int gt   = blockIdx.x * blockDim.x + threadIdx.x;
    int n    = gt >> 5;
    int lane = gt & 31;
    if (n >= NN) return;
    const int qw = lane >> 3;      // quarter-warp 0..3
    const int li = lane & 7;       // 8 lanes x 16B = 128B row

    float acc[8];
    #pragma unroll
    for (int i = 0; i < 8; i++) acc[i] = 0.f;

    #pragma unroll
    for (int r = 0; r < RR; r++) {
        int key = r * NN + n;
        int beg = g_rowptr[key];
        int end = g_rowptr[key + 1];
        const __half* Yr = g_Y2h + (size_t)r * NN * DOUT;
        float s[8];
        #pragma unroll
        for (int i = 0; i < 8; i++) s[i] = 0.f;

        for (int j = beg + qw; j < end; j += 4) {   // 4 rows in flight per warp
            int sn = g_colsrc[j];
            uint4 u = *(const uint4*)&Yr[(size_t)sn * DOUT + li * 8];
            float2 a0 = __half22float2(*(const __half2*)&u.x);
            float2 a1 = __half22float2(*(const __half2*)&u.y);
            float2 a2 = __half22float2(*(const __half2*)&u.z);
            float2 a3 = __half22float2(*(const __half2*)&u.w);
            s[0] += a0.x; s[1] += a0.y; s[2] += a1.x; s[3] += a1.y;
            s[4] += a2.x; s[5] += a2.y; s[6] += a3.x; s[7] += a3.y;
        }
        float inn = g_inorm[key];
        #pragma unroll
        for (int i = 0; i < 8; i++) acc[i] += inn * s[i];
    }
    // reduce across the 4 quarter-warps
    #pragma unroll
    for (int i = 0; i < 8; i++) {
        acc[i] += __shfl_xor_sync(0xffffffffu, acc[i], 8);
        acc[i] += __shfl_xor_sync(0xffffffffu, acc[i], 16);
    }
    int col = li * 8;
    #pragma unroll
    for (int i = 0; i < 8; i++)
        acc[i] += b2[col + i] + b2[DOUT + col + i] + b2[2 * DOUT + col + i];
    if (qw == 0) {
        float4* dst = (float4*)&out[(size_t)n * DOUT + col];
        dst[0] = make_float4(acc[0], acc[1], acc[2], acc[3]);
        dst[1] = make_float4(acc[4], acc[5], acc[6], acc[7]);
    }
}

// ---------------- launch -----------------------------------------------------
extern "C" void kernel_launch(void* const* d_in, const int* in_sizes, int n_in,
                              void* d_out, int out_size) {
    const float* x   = (const float*)d_in[0];
    const float* W1  = (const float*)d_in[1];
    const float* b1  = (const float*)d_in[2];
    const float* W2  = (const float*)d_in[3];
    const float* b2  = (const float*)d_in[4];
    const int*   src = (const int*)d_in[5];
    const int*   dst = (const int*)d_in[6];
    float*       out = (float*)d_out;

    __half *w1t, *w2t;
    cudaGetSymbolAddress((void**)&w1t, g_W1T);
    cudaGetSymbolAddress((void**)&w2t, g_W2T);

    // one-time host resources (no device memory involved)
    static cudaStream_t s2 = nullptr;
    static cudaEvent_t  evFork = nullptr, evNorm = nullptr, evPre = nullptr;
    if (s2 == nullptr) {
        cudaStreamCreateWithFlags(&s2, cudaStreamNonBlocking);
        cudaEventCreateWithFlags(&evFork, cudaEventDisableTiming);
        cudaEventCreateWithFlags(&evNorm, cudaEventDisableTiming);
        cudaEventCreateWithFlags(&evPre,  cudaEventDisableTiming);
    }

    const int SMEM1 = 128 * 256 + 2 * (128 * 256);   // 98304
    const int SMEM2 = 128 * 256 + 2 * ( 64 * 256);   // 65536
    cudaFuncSetAttribute(mma_gemm_fused<128, 0>,
                         cudaFuncAttributeMaxDynamicSharedMemorySize, SMEM1);
    cudaFuncSetAttribute(mma_gemm_fused<64, 1>,
                         cudaFuncAttributeMaxDynamicSharedMemorySize, SMEM2);

    // ---- fork: graph preprocessing on side stream ----
    cudaEventRecord(evFork, 0);
    cudaStreamWaitEvent(s2, evFork, 0);
    zero_deg_kernel <<<(RN + 255) / 256, 256, 0, s2>>>();
    count_deg_kernel<<<dim3((EE + 255) / 256, RR), 256, 0, s2>>>(src, dst);
    onorm_kernel    <<<(RN + 255) / 256, 256, 0, s2>>>();
    cudaEventRecord(evNorm, s2);                     // onorm ready for GEMM1
    scan1_kernel    <<<NB, 1024, 0, s2>>>();
    scan2_kernel    <<<1, 256, 0, s2>>>();
    scan3_kernel    <<<(RN + 255) / 256, 256, 0, s2>>>();  // + inorm
    fill_csr_kernel <<<dim3((EE + 255) / 256, RR), 256, 0, s2>>>(src, dst);
    cudaEventRecord(evPre, s2);

    // ---- main stream: weight transpose overlaps count/norm ----
    wtrans_kernel<DHID><<<dim3((128 * DHID + 255) / 256, RR), 256>>>(W1, w1t);
    wtrans_kernel<DOUT><<<dim3((128 * DOUT + 255) / 256, RR), 256>>>(W2, w2t);

    // layer-1 fused GEMM (all relations) needs onorm; CSR build overlaps it
    cudaStreamWaitEvent(0, evNorm, 0);
    mma_gemm_fused<128, 0><<<(NN + 127) / 128, 256, SMEM1>>>(x);

    // ---- join: aggregation needs CSR + inorm ----
    cudaStreamWaitEvent(0, evPre, 0);
    agg1_kernel<<<(NN * 32 + 255) / 256, 256>>>(b1);

    // layer 2
    mma_gemm_fused<64, 1><<<(NN + 127) / 128, 256, SMEM2>>>(nullptr);
    agg2_kernel<<<(NN * 32 + 255) / 256, 256>>>(b2, out);
}